// round 13
// baseline (speedup 1.0000x reference)
#include <cuda_runtime.h>
#include <cuda_fp16.h>
#include <stdint.h>

// ---------------- problem constants ----------------
#define BS    256
#define SEQ   4096
#define DD    128
#define NCATS 256
#define GCOLS 384

// ---------------- device scratch ----------------
__device__ __half g_Hh[(size_t)BS * SEQ * DD];   // hidden history, fp16 (for logits GEMM)
__device__ float  g_proj4[257 * DD * 4];         // per-token xi: [tok][d][{xr,xz,xn,0}]
__device__ __half g_WcT[NCATS * DD];             // W_cls transposed -> [cat][d], fp16
__device__ int    g_is64;

// ---------------- helpers ----------------
__device__ __forceinline__ uint32_t smem_u32(const void* p) {
    uint32_t a;
    asm("{ .reg .u64 t; cvta.to.shared.u64 t, %1; cvt.u32.u64 %0, t; }" : "=r"(a) : "l"(p));
    return a;
}
__device__ __forceinline__ uint32_t packh2(float a, float b) {
    __half2 h = __floats2half2_rn(a, b);
    return *reinterpret_cast<uint32_t*>(&h);
}
__device__ __forceinline__ void mma16816(float* d, const uint32_t* a, const uint32_t* b) {
    asm volatile(
        "mma.sync.aligned.m16n8k16.row.col.f32.f16.f16.f32 "
        "{%0,%1,%2,%3}, {%4,%5,%6,%7}, {%8,%9}, {%0,%1,%2,%3};\n"
        : "+f"(d[0]), "+f"(d[1]), "+f"(d[2]), "+f"(d[3])
        : "r"(a[0]), "r"(a[1]), "r"(a[2]), "r"(a[3]), "r"(b[0]), "r"(b[1]));
}
__device__ __forceinline__ void ldsm_x4(uint32_t* r, uint32_t addr) {
    asm volatile("ldmatrix.sync.aligned.m8n8.x4.shared.b16 {%0,%1,%2,%3}, [%4];"
                 : "=r"(r[0]), "=r"(r[1]), "=r"(r[2]), "=r"(r[3]) : "r"(addr));
}
__device__ __forceinline__ float ex2f(float x) {
    float y; asm("ex2.approx.f32 %0, %1;" : "=f"(y) : "f"(x)); return y;
}
__device__ __forceinline__ float rcpf(float x) {
    float y; asm("rcp.approx.f32 %0, %1;" : "=f"(y) : "f"(x)); return y;
}
__device__ __forceinline__ float sigf(float x) {
    return rcpf(1.f + ex2f(-1.4426950408889634f * x));
}
__device__ __forceinline__ float tanhf_fast(float x) {
    return 1.f - 2.f * rcpf(1.f + ex2f(2.8853900817779268f * x));
}

// ---------------- kernel 1: int64/int32 detection ----------------
__global__ void detect_kernel(const unsigned int* xw) {
    __shared__ unsigned int s[256];
    unsigned int v = 0;
    for (int i = threadIdx.x; i < 4096; i += 256) v |= xw[2 * i + 1];
    s[threadIdx.x] = v;
    __syncthreads();
    if (threadIdx.x == 0) {
        unsigned int a = 0;
        for (int i = 0; i < 256; i++) a |= s[i];
        g_is64 = (a == 0) ? 1 : 0;
    }
}

// ---------------- kernel 2: proj4[c][d] = (xr, xz, xn, 0) ----------------
__global__ void __launch_bounds__(DD) proj_kernel(const float* __restrict__ emb,
                                                  const float* __restrict__ Wi,
                                                  const float* __restrict__ bi) {
    __shared__ float e[DD];
    const int c = blockIdx.x;
    const int j = threadIdx.x;
    e[j] = emb[c * DD + j];
    __syncthreads();
    float a0 = bi[j], a1 = bi[DD + j], a2 = bi[2 * DD + j];
#pragma unroll 8
    for (int k = 0; k < DD; k++) {
        float ek = e[k];
        a0 += ek * Wi[k * GCOLS + j];
        a1 += ek * Wi[k * GCOLS + DD + j];
        a2 += ek * Wi[k * GCOLS + 2 * DD + j];
    }
    float4* o = (float4*)&g_proj4[(size_t)(c * DD + j) * 4];
    *o = make_float4(a0, a1, a2, 0.f);
}

// ---------------- kernel 2b: W_cls -> fp16 transposed ----------------
__global__ void prep_wc(const float* __restrict__ Wcls) {
    int i = blockIdx.x * 256 + threadIdx.x;      // 32768
    int d = i / NCATS, c = i % NCATS;
    g_WcT[c * DD + d] = __float2half_rn(Wcls[d * NCATS + c]);
}

// ---------------- scan building blocks ----------------
#define HTP 136   // padded hT row (halves)

// 24 MMAs into 6 independent chains (kt parity split), acc reset inside.
__device__ __forceinline__ void issue_mma(float acc[3][2][4],
                                          const uint32_t A[3][8][4],
                                          const char* hb) {
#pragma unroll
    for (int s = 0; s < 3; s++)
#pragma unroll
        for (int p = 0; p < 4; p++) { acc[s][0][p] = 0.f; acc[s][1][p] = 0.f; }
#pragma unroll
    for (int kt = 0; kt < 8; kt++) {
        uint32_t b[2];
        b[0] = *(const uint32_t*)(hb + kt * 32);
        b[1] = *(const uint32_t*)(hb + kt * 32 + 16);
#pragma unroll
        for (int s = 0; s < 3; s++) mma16816(acc[s][kt & 1], A[s][kt], b);
    }
}

// register select of this lane's (d,row) pre-activations + gates (R12 math).
__device__ __forceinline__ float gate_update(const float acc[3][2][4], int q,
                                             float4 xi, float h, float bn) {
    float pr, pz, pn;
    {
        float e0, e1;
        e0 = (q & 2) ? acc[0][0][2] : acc[0][0][0];
        e1 = (q & 2) ? acc[0][0][3] : acc[0][0][1];
        pr = ((q & 1) ? e1 : e0);
        e0 = (q & 2) ? acc[0][1][2] : acc[0][1][0];
        e1 = (q & 2) ? acc[0][1][3] : acc[0][1][1];
        pr += ((q & 1) ? e1 : e0);

        e0 = (q & 2) ? acc[1][0][2] : acc[1][0][0];
        e1 = (q & 2) ? acc[1][0][3] : acc[1][0][1];
        pz = ((q & 1) ? e1 : e0);
        e0 = (q & 2) ? acc[1][1][2] : acc[1][1][0];
        e1 = (q & 2) ? acc[1][1][3] : acc[1][1][1];
        pz += ((q & 1) ? e1 : e0);

        e0 = (q & 2) ? acc[2][0][2] : acc[2][0][0];
        e1 = (q & 2) ? acc[2][0][3] : acc[2][0][1];
        pn = ((q & 1) ? e1 : e0);
        e0 = (q & 2) ? acc[2][1][2] : acc[2][1][0];
        e1 = (q & 2) ? acc[2][1][3] : acc[2][1][1];
        pn += ((q & 1) ? e1 : e0);
    }
    float R = sigf(xi.x + pr);
    float Z = sigf(xi.y + pz);
    float N = tanhf_fast(xi.z + R * (pn + bn));
    return N + Z * (h - N);
}

// ---------------- kernel 3: HMMA GRU scan, 64 CTAs x 4 rows, 2-group pipeline ----------------
// Groups A = rows {4b,4b+1}, B = rows {4b+2,4b+3}. Iteration t:
//   MMA_B(t) -> epi_A(t) -> bar -> MMA_A(t+1) -> epi_B(t) -> bar
// Every group's MMA result drains across the other group's epilogue + a barrier
// before its selects read it: exposed MMA latency ~0.
__global__ void __launch_bounds__(256, 1)
scan_kernel(const int* __restrict__ xw,
            const float* __restrict__ Whrz,
            const float* __restrict__ Whn,
            const float* __restrict__ bhn,
            const float* __restrict__ initst) {
    __shared__ __half hT[2][4][HTP];    // [buf][phys row: A=0..1, B=2..3][k]

    const int tid = threadIdx.x;
    const int w = tid >> 5, l = tid & 31;
    const int gr = l >> 2, q = l & 3;
    const int row0 = blockIdx.x * 4;
    const int d   = w * 16 + gr + ((q & 2) ? 8 : 0);  // this lane's gate dim
    const int row = q & 1;                            // row within group

    // ---- A fragments (validated remap): warp w holds r,z,n for its d-range ----
    uint32_t A[3][8][4];
    {
        const int kc = q * 2;
#pragma unroll
        for (int s = 0; s < 3; s++) {
#pragma unroll
            for (int kt = 0; kt < 8; kt++) {
                const int k0 = kt * 16 + kc;
                float a00, a01, a10, a11, a20, a21, a30, a31;
                if (s == 2) {
                    int ga = w * 16 + gr, gb = ga + 8;
                    a00 = Whn[k0 * DD + ga];       a01 = Whn[(k0 + 1) * DD + ga];
                    a10 = Whn[k0 * DD + gb];       a11 = Whn[(k0 + 1) * DD + gb];
                    a20 = Whn[(k0 + 8) * DD + ga]; a21 = Whn[(k0 + 9) * DD + ga];
                    a30 = Whn[(k0 + 8) * DD + gb]; a31 = Whn[(k0 + 9) * DD + gb];
                } else {
                    int ga = s * 128 + w * 16 + gr, gb = ga + 8;
                    a00 = Whrz[k0 * 256 + ga];       a01 = Whrz[(k0 + 1) * 256 + ga];
                    a10 = Whrz[k0 * 256 + gb];       a11 = Whrz[(k0 + 1) * 256 + gb];
                    a20 = Whrz[(k0 + 8) * 256 + ga]; a21 = Whrz[(k0 + 9) * 256 + ga];
                    a30 = Whrz[(k0 + 8) * 256 + gb]; a31 = Whrz[(k0 + 9) * 256 + gb];
                }
                A[s][kt][0] = packh2(a00, a01);
                A[s][kt][1] = packh2(a10, a11);
                A[s][kt][2] = packh2(a20, a21);
                A[s][kt][3] = packh2(a30, a31);
            }
        }
    }

    // ---- init both groups ----
    const float bn = bhn[d];
    float hA = initst[d], hB = hA;
    hT[0][row][d]     = __float2half_rn(hA);
    hT[0][2 + row][d] = __float2half_rn(hB);
    float4 xiA = *(const float4*)&g_proj4[(size_t)(NCATS * DD + d) * 4];   // BOS
    float4 xiB = xiA;
    const int is64 = g_is64;
    const int xbaseA = (row0 + row) * SEQ;
    const int xbaseB = (row0 + 2 + row) * SEQ;
    int tokA = is64 ? xw[2 * xbaseA] : xw[xbaseA];
    int tokB = is64 ? xw[2 * xbaseB] : xw[xbaseB];
    __syncthreads();

    // lane's B-fragment byte offsets (n-col (l>>2) -> phys row ((l>>2)&1) [+2 for B])
    const uint32_t bOffA = (uint32_t)(((l >> 2) & 1) * (HTP * 2) + q * 4);
    const uint32_t bOffB = bOffA + (uint32_t)(2 * HTP * 2);
    const char* hTb = (const char*)hT;
    const uint32_t BUFS = 4 * HTP * 2;   // bytes per buffer

    float accA[3][2][4], accB[3][2][4];
    issue_mma(accA, A, hTb + bOffA);     // MMA_A for t=0 (buf 0)

    for (int t = 0; t < SEQ; t++) {
        // ---- MMA_B(t) ----
        issue_mma(accB, A, hTb + (uint32_t)((t & 1) * BUFS) + bOffB);

        // ---- epilogue A(t): accA drained across previous half-iteration ----
        {
            float4 xin = *(const float4*)&g_proj4[(size_t)(tokA * DD + d) * 4];
            int tokn = tokA;
            if (t + 1 < SEQ) {
                int idx = xbaseA + t + 1;
                tokn = is64 ? xw[2 * idx] : xw[idx];
            }
            hA = gate_update(accA, q, xiA, hA, bn);
            __half hh = __float2half_rn(hA);
            g_Hh[((size_t)(row0 + row) * SEQ + t) * DD + d] = hh;
            hT[(t + 1) & 1][row][d] = hh;
            xiA = xin; tokA = tokn;
        }
        __syncthreads();                 // hT_A(t+1) visible

        // ---- MMA_A(t+1) ----
        if (t + 1 < SEQ)
            issue_mma(accA, A, hTb + (uint32_t)(((t + 1) & 1) * BUFS) + bOffA);

        // ---- epilogue B(t) ----
        {
            float4 xin = *(const float4*)&g_proj4[(size_t)(tokB * DD + d) * 4];
            int tokn = tokB;
            if (t + 1 < SEQ) {
                int idx = xbaseB + t + 1;
                tokn = is64 ? xw[2 * idx] : xw[idx];
            }
            hB = gate_update(accB, q, xiB, hB, bn);
            __half hh = __float2half_rn(hB);
            g_Hh[((size_t)(row0 + 2 + row) * SEQ + t) * DD + d] = hh;
            hT[(t + 1) & 1][2 + row][d] = hh;
            xiB = xin; tokB = tokn;
        }
        __syncthreads();                 // hT_B(t+1) visible
    }
}

// ---------------- kernel 4: logits = H @ W_cls + b_cls via HMMA (R11) ----------------
#define HPAD 136
__global__ void __launch_bounds__(512, 1) logits_kernel(const float* __restrict__ bcls,
                                                        float* __restrict__ out) {
    extern __shared__ __half sh[];
    __half* Hs = sh;                    // [128][HPAD]
    __half* Wc = sh + 128 * HPAD;       // [256][HPAD]  (WcT: [cat][d])
    const int tid = threadIdx.x;
    const int batch = blockIdx.y;
    const int t0 = blockIdx.x * 128;

    const __half* hsrc = &g_Hh[((size_t)batch * SEQ + t0) * DD];
    for (int i = tid; i < 128 * 16; i += 512) {
        int rr = i >> 4, c8 = (i & 15) * 8;
        *(float4*)&Hs[rr * HPAD + c8] = *(const float4*)&hsrc[rr * DD + c8];
    }
    for (int i = tid; i < 256 * 16; i += 512) {
        int rr = i >> 4, c8 = (i & 15) * 8;
        *(float4*)&Wc[rr * HPAD + c8] = *(const float4*)&g_WcT[rr * DD + c8];
    }
    __syncthreads();

    const int w = tid >> 5, l = tid & 31;
    const int m0 = (w >> 2) * 32;       // 4 m-groups of 32 rows
    const int n0 = (w & 3) * 64;        // 4 n-groups of 64 cats

    float acc[2][8][4];
#pragma unroll
    for (int nt = 0; nt < 8; nt++) {
        float b0 = bcls[n0 + nt * 8 + (l & 3) * 2];
        float b1 = bcls[n0 + nt * 8 + (l & 3) * 2 + 1];
#pragma unroll
        for (int mt = 0; mt < 2; mt++) {
            acc[mt][nt][0] = b0; acc[mt][nt][1] = b1;
            acc[mt][nt][2] = b0; acc[mt][nt][3] = b1;
        }
    }

    const uint32_t hs_u32 = smem_u32(Hs);
    const int arow = m0 + (l & 15);
    const int acol = (l >> 4) * 8;
#pragma unroll
    for (int kt = 0; kt < 8; kt++) {
        uint32_t Af[2][4];
#pragma unroll
        for (int mt = 0; mt < 2; mt++)
            ldsm_x4(Af[mt], hs_u32 + (uint32_t)(((arow + mt * 16) * HPAD + kt * 16 + acol) * 2));
        uint32_t Bf[8][2];
#pragma unroll
        for (int nt = 0; nt < 8; nt++) {
            const __half* wp = &Wc[(n0 + nt * 8 + (l >> 2)) * HPAD + kt * 16 + (l & 3) * 2];
            Bf[nt][0] = *(const uint32_t*)wp;
            Bf[nt][1] = *(const uint32_t*)(wp + 8);
        }
#pragma unroll
        for (int mt = 0; mt < 2; mt++)
#pragma unroll
            for (int nt = 0; nt < 8; nt++) mma16816(acc[mt][nt], Af[mt], Bf[nt]);
    }

    const size_t obase = ((size_t)batch * SEQ + t0) * NCATS;
#pragma unroll
    for (int mt = 0; mt < 2; mt++) {
        const int rrow = m0 + mt * 16 + (l >> 2);
#pragma unroll
        for (int nt = 0; nt < 8; nt++) {
            const int col = n0 + nt * 8 + (l & 3) * 2;
            *(float2*)&out[obase + (size_t)rrow * NCATS + col] =
                make_float2(acc[mt][nt][0], acc[mt][nt][1]);
            *(float2*)&out[obase + (size_t)(rrow + 8) * NCATS + col] =
                make_float2(acc[mt][nt][2], acc[mt][nt][3]);
        }
    }
}

// ---------------- launch ----------------
extern "C" void kernel_launch(void* const* d_in, const int* in_sizes, int n_in,
                              void* d_out, int out_size) {
    const void*  x      = d_in[0];
    const float* emb    = (const float*)d_in[1];
    const float* Wi     = (const float*)d_in[2];
    const float* bi     = (const float*)d_in[3];
    const float* Whrz   = (const float*)d_in[4];
    const float* Whn    = (const float*)d_in[5];
    const float* bhn    = (const float*)d_in[6];
    const float* Wcls   = (const float*)d_in[7];
    const float* bcls   = (const float*)d_in[8];
    const float* initst = (const float*)d_in[9];
    float* out = (float*)d_out;

    const int LOG_SMEM = (128 + 256) * HPAD * (int)sizeof(__half);   // 104448 B
    cudaFuncSetAttribute(logits_kernel, cudaFuncAttributeMaxDynamicSharedMemorySize, LOG_SMEM);

    detect_kernel<<<1, 256>>>((const unsigned int*)x);
    proj_kernel<<<257, DD>>>(emb, Wi, bi);
    prep_wc<<<(NCATS * DD) / 256, 256>>>(Wcls);
    scan_kernel<<<BS / 4, 256>>>((const int*)x, Whrz, Whn, bhn, initst);
    logits_kernel<<<dim3(SEQ / 128, BS), 512, LOG_SMEM>>>(bcls, out);
}

// round 14
// speedup vs baseline: 1.8313x; 1.8313x over previous
#include <cuda_runtime.h>
#include <cuda_fp16.h>
#include <stdint.h>

// ---------------- problem constants ----------------
#define BS    256
#define SEQ   4096
#define DD    128
#define NCATS 256
#define GCOLS 384

// ---------------- device scratch ----------------
__device__ __half g_Hh[(size_t)BS * SEQ * DD];   // hidden history, fp16 (for logits GEMM)
__device__ float  g_proj4[257 * DD * 4];         // per-token xi: [tok][d][{xr,xz,xn,0}]
__device__ __half g_WcT[NCATS * DD];             // W_cls transposed -> [cat][d], fp16
__device__ int    g_is64;

// ---------------- helpers ----------------
__device__ __forceinline__ uint32_t smem_u32(const void* p) {
    uint32_t a;
    asm("{ .reg .u64 t; cvta.to.shared.u64 t, %1; cvt.u32.u64 %0, t; }" : "=r"(a) : "l"(p));
    return a;
}
__device__ __forceinline__ uint32_t packh2(float a, float b) {
    __half2 h = __floats2half2_rn(a, b);
    return *reinterpret_cast<uint32_t*>(&h);
}
__device__ __forceinline__ void mma16816(float* d, const uint32_t* a, const uint32_t* b) {
    asm volatile(
        "mma.sync.aligned.m16n8k16.row.col.f32.f16.f16.f32 "
        "{%0,%1,%2,%3}, {%4,%5,%6,%7}, {%8,%9}, {%0,%1,%2,%3};\n"
        : "+f"(d[0]), "+f"(d[1]), "+f"(d[2]), "+f"(d[3])
        : "r"(a[0]), "r"(a[1]), "r"(a[2]), "r"(a[3]), "r"(b[0]), "r"(b[1]));
}
__device__ __forceinline__ void ldsm_x4(uint32_t* r, uint32_t addr) {
    asm volatile("ldmatrix.sync.aligned.m8n8.x4.shared.b16 {%0,%1,%2,%3}, [%4];"
                 : "=r"(r[0]), "=r"(r[1]), "=r"(r[2]), "=r"(r[3]) : "r"(addr));
}
__device__ __forceinline__ float ex2f(float x) {
    float y; asm("ex2.approx.f32 %0, %1;" : "=f"(y) : "f"(x)); return y;
}
__device__ __forceinline__ float rcpf(float x) {
    float y; asm("rcp.approx.f32 %0, %1;" : "=f"(y) : "f"(x)); return y;
}
__device__ __forceinline__ float sigf(float x) {
    return rcpf(1.f + ex2f(-1.4426950408889634f * x));
}
__device__ __forceinline__ float tanhf_fast(float x) {
    return 1.f - 2.f * rcpf(1.f + ex2f(2.8853900817779268f * x));
}

// ---------------- kernel 1: int64/int32 detection ----------------
__global__ void detect_kernel(const unsigned int* xw) {
    __shared__ unsigned int s[256];
    unsigned int v = 0;
    for (int i = threadIdx.x; i < 4096; i += 256) v |= xw[2 * i + 1];
    s[threadIdx.x] = v;
    __syncthreads();
    if (threadIdx.x == 0) {
        unsigned int a = 0;
        for (int i = 0; i < 256; i++) a |= s[i];
        g_is64 = (a == 0) ? 1 : 0;
    }
}

// ---------------- kernel 2: proj4[c][d] = (xr, xz, xn, 0) ----------------
__global__ void __launch_bounds__(DD) proj_kernel(const float* __restrict__ emb,
                                                  const float* __restrict__ Wi,
                                                  const float* __restrict__ bi) {
    __shared__ float e[DD];
    const int c = blockIdx.x;
    const int j = threadIdx.x;
    e[j] = emb[c * DD + j];
    __syncthreads();
    float a0 = bi[j], a1 = bi[DD + j], a2 = bi[2 * DD + j];
#pragma unroll 8
    for (int k = 0; k < DD; k++) {
        float ek = e[k];
        a0 += ek * Wi[k * GCOLS + j];
        a1 += ek * Wi[k * GCOLS + DD + j];
        a2 += ek * Wi[k * GCOLS + 2 * DD + j];
    }
    float4* o = (float4*)&g_proj4[(size_t)(c * DD + j) * 4];
    *o = make_float4(a0, a1, a2, 0.f);
}

// ---------------- kernel 2b: W_cls -> fp16 transposed ----------------
__global__ void prep_wc(const float* __restrict__ Wcls) {
    int i = blockIdx.x * 256 + threadIdx.x;      // 32768
    int d = i / NCATS, c = i % NCATS;
    g_WcT[c * DD + d] = __float2half_rn(Wcls[d * NCATS + c]);
}

// ---------------- kernel 3: HMMA GRU scan, 128 CTAs x 2 rows (R12 + lean epilogue) ----------------
// Warp w owns r,z,n for d in [16w,16w+16); B n-col -> physical row (n&1); register
// select epilogue; double-buffered hT; ONE __syncthreads per step.
// R14 edits: s={0,1} MMAs first then s=2 (R/Z math overlaps s2 drain); xi/token
// prefetch issued BEFORE the MMA block; g_Hh STG deferred into next step's shadow.
#define HTP 136   // padded hT row (halves) -> 272B stride
__global__ void __launch_bounds__(256, 1)
scan_kernel(const int* __restrict__ xw,
            const float* __restrict__ Whrz,
            const float* __restrict__ Whn,
            const float* __restrict__ bhn,
            const float* __restrict__ initst) {
    __shared__ __half hT[2][2][HTP];    // [buf][row][k]

    const int tid = threadIdx.x;
    const int w = tid >> 5, l = tid & 31;
    const int gr = l >> 2, q = l & 3;
    const int row0 = blockIdx.x * 2;
    const int d   = w * 16 + gr + ((q & 2) ? 8 : 0);  // this lane's gate dim
    const int row = q & 1;                            // this lane's batch row

    // ---- A fragments: warp w holds r,z,n for its d-range ----
    uint32_t A[3][8][4];
    {
        const int kc = q * 2;
#pragma unroll
        for (int s = 0; s < 3; s++) {
#pragma unroll
            for (int kt = 0; kt < 8; kt++) {
                const int k0 = kt * 16 + kc;
                float a00, a01, a10, a11, a20, a21, a30, a31;
                if (s == 2) {
                    int ga = w * 16 + gr, gb = ga + 8;
                    a00 = Whn[k0 * DD + ga];       a01 = Whn[(k0 + 1) * DD + ga];
                    a10 = Whn[k0 * DD + gb];       a11 = Whn[(k0 + 1) * DD + gb];
                    a20 = Whn[(k0 + 8) * DD + ga]; a21 = Whn[(k0 + 9) * DD + ga];
                    a30 = Whn[(k0 + 8) * DD + gb]; a31 = Whn[(k0 + 9) * DD + gb];
                } else {
                    int ga = s * 128 + w * 16 + gr, gb = ga + 8;
                    a00 = Whrz[k0 * 256 + ga];       a01 = Whrz[(k0 + 1) * 256 + ga];
                    a10 = Whrz[k0 * 256 + gb];       a11 = Whrz[(k0 + 1) * 256 + gb];
                    a20 = Whrz[(k0 + 8) * 256 + ga]; a21 = Whrz[(k0 + 9) * 256 + ga];
                    a30 = Whrz[(k0 + 8) * 256 + gb]; a31 = Whrz[(k0 + 9) * 256 + gb];
                }
                A[s][kt][0] = packh2(a00, a01);
                A[s][kt][1] = packh2(a10, a11);
                A[s][kt][2] = packh2(a20, a21);
                A[s][kt][3] = packh2(a30, a31);
            }
        }
    }

    // ---- init ----
    float h = initst[d];
    const float bn = bhn[d];
    hT[0][row][d] = __float2half_rn(h);
    float4 xi = *(const float4*)&g_proj4[(size_t)(NCATS * DD + d) * 4];   // BOS
    const int is64 = g_is64;
    const int xbase = (row0 + row) * SEQ;
    int tok = is64 ? xw[2 * xbase] : xw[xbase];
    __half* const hout = &g_Hh[(size_t)(row0 + row) * SEQ * DD + d];
    __half hh_prev = __float2half(0.f);
    __syncthreads();

    // lane's B-fragment base: n-col (l>>2) -> physical row (l>>2)&1 (broadcast)
    const uint32_t bOff = (uint32_t)(((l >> 2) & 1) * (HTP * 2) + q * 4);

    for (int t = 0; t < SEQ; t++) {
        // ---- B fragments from hT[t&1] ----
        const char* hb = (const char*)hT + (uint32_t)((t & 1) * (2 * HTP * 2)) + bOff;
        uint32_t b[8][2];
#pragma unroll
        for (int kt = 0; kt < 8; kt++) {
            b[kt][0] = *(const uint32_t*)(hb + kt * 32);
            b[kt][1] = *(const uint32_t*)(hb + kt * 32 + 16);
        }

        // ---- prefetch xi(t+1)/token(t+2) BEFORE MMAs: L2 latency hides under them ----
        float4 xin = *(const float4*)&g_proj4[(size_t)(tok * DD + d) * 4];
        int tokn = tok;
        if (t + 1 < SEQ) {
            int idx = xbase + t + 1;
            tokn = is64 ? xw[2 * idx] : xw[idx];
        }
        // ---- deferred STG of h(t-1) in the MMA shadow ----
        if (t > 0) hout[(size_t)(t - 1) * DD] = hh_prev;

        // ---- MMAs: s=0,1 (r,z) first ----
        float acc[3][2][4];
#pragma unroll
        for (int s = 0; s < 3; s++)
#pragma unroll
            for (int p = 0; p < 4; p++) { acc[s][0][p] = 0.f; acc[s][1][p] = 0.f; }
#pragma unroll
        for (int kt = 0; kt < 8; kt++) {
            mma16816(acc[0][kt & 1], A[0][kt], b[kt]);
            mma16816(acc[1][kt & 1], A[1][kt], b[kt]);
        }
        // ---- s=2 (n) last: its drain overlaps the R/Z math below ----
#pragma unroll
        for (int kt = 0; kt < 8; kt++)
            mma16816(acc[2][kt & 1], A[2][kt], b[kt]);

        // ---- R/Z: selects + sigmoids while s=2 drains ----
        float pr, pz;
        {
            float e0, e1;
            e0 = (q & 2) ? acc[0][0][2] : acc[0][0][0];
            e1 = (q & 2) ? acc[0][0][3] : acc[0][0][1];
            pr = ((q & 1) ? e1 : e0);
            e0 = (q & 2) ? acc[0][1][2] : acc[0][1][0];
            e1 = (q & 2) ? acc[0][1][3] : acc[0][1][1];
            pr += ((q & 1) ? e1 : e0);

            e0 = (q & 2) ? acc[1][0][2] : acc[1][0][0];
            e1 = (q & 2) ? acc[1][0][3] : acc[1][0][1];
            pz = ((q & 1) ? e1 : e0);
            e0 = (q & 2) ? acc[1][1][2] : acc[1][1][0];
            e1 = (q & 2) ? acc[1][1][3] : acc[1][1][1];
            pz += ((q & 1) ? e1 : e0);
        }
        float R = sigf(xi.x + pr);
        float Z = sigf(xi.y + pz);

        // ---- N path ----
        float pn;
        {
            float e0, e1;
            e0 = (q & 2) ? acc[2][0][2] : acc[2][0][0];
            e1 = (q & 2) ? acc[2][0][3] : acc[2][0][1];
            pn = ((q & 1) ? e1 : e0);
            e0 = (q & 2) ? acc[2][1][2] : acc[2][1][0];
            e1 = (q & 2) ? acc[2][1][3] : acc[2][1][1];
            pn += ((q & 1) ? e1 : e0);
        }
        float N = tanhf_fast(xi.z + R * (pn + bn));
        h = N + Z * (h - N);

        hh_prev = __float2half_rn(h);
        hT[(t + 1) & 1][row][d] = hh_prev;   // write NEXT buffer
        xi = xin; tok = tokn;
        __syncthreads();                     // ONE barrier per step
    }
    hout[(size_t)(SEQ - 1) * DD] = hh_prev;  // tail store
}

// ---------------- kernel 4: logits = H @ W_cls + b_cls via HMMA (R11) ----------------
#define HPAD 136
__global__ void __launch_bounds__(512, 1) logits_kernel(const float* __restrict__ bcls,
                                                        float* __restrict__ out) {
    extern __shared__ __half sh[];
    __half* Hs = sh;                    // [128][HPAD]
    __half* Wc = sh + 128 * HPAD;       // [256][HPAD]  (WcT: [cat][d])
    const int tid = threadIdx.x;
    const int batch = blockIdx.y;
    const int t0 = blockIdx.x * 128;

    const __half* hsrc = &g_Hh[((size_t)batch * SEQ + t0) * DD];
    for (int i = tid; i < 128 * 16; i += 512) {
        int rr = i >> 4, c8 = (i & 15) * 8;
        *(float4*)&Hs[rr * HPAD + c8] = *(const float4*)&hsrc[rr * DD + c8];
    }
    for (int i = tid; i < 256 * 16; i += 512) {
        int rr = i >> 4, c8 = (i & 15) * 8;
        *(float4*)&Wc[rr * HPAD + c8] = *(const float4*)&g_WcT[rr * DD + c8];
    }
    __syncthreads();

    const int w = tid >> 5, l = tid & 31;
    const int m0 = (w >> 2) * 32;       // 4 m-groups of 32 rows
    const int n0 = (w & 3) * 64;        // 4 n-groups of 64 cats

    float acc[2][8][4];
#pragma unroll
    for (int nt = 0; nt < 8; nt++) {
        float b0 = bcls[n0 + nt * 8 + (l & 3) * 2];
        float b1 = bcls[n0 + nt * 8 + (l & 3) * 2 + 1];
#pragma unroll
        for (int mt = 0; mt < 2; mt++) {
            acc[mt][nt][0] = b0; acc[mt][nt][1] = b1;
            acc[mt][nt][2] = b0; acc[mt][nt][3] = b1;
        }
    }

    const uint32_t hs_u32 = smem_u32(Hs);
    const int arow = m0 + (l & 15);
    const int acol = (l >> 4) * 8;
#pragma unroll
    for (int kt = 0; kt < 8; kt++) {
        uint32_t Af[2][4];
#pragma unroll
        for (int mt = 0; mt < 2; mt++)
            ldsm_x4(Af[mt], hs_u32 + (uint32_t)(((arow + mt * 16) * HPAD + kt * 16 + acol) * 2));
        uint32_t Bf[8][2];
#pragma unroll
        for (int nt = 0; nt < 8; nt++) {
            const __half* wp = &Wc[(n0 + nt * 8 + (l >> 2)) * HPAD + kt * 16 + (l & 3) * 2];
            Bf[nt][0] = *(const uint32_t*)wp;
            Bf[nt][1] = *(const uint32_t*)(wp + 8);
        }
#pragma unroll
        for (int mt = 0; mt < 2; mt++)
#pragma unroll
            for (int nt = 0; nt < 8; nt++) mma16816(acc[mt][nt], Af[mt], Bf[nt]);
    }

    const size_t obase = ((size_t)batch * SEQ + t0) * NCATS;
#pragma unroll
    for (int mt = 0; mt < 2; mt++) {
        const int rrow = m0 + mt * 16 + (l >> 2);
#pragma unroll
        for (int nt = 0; nt < 8; nt++) {
            const int col = n0 + nt * 8 + (l & 3) * 2;
            *(float2*)&out[obase + (size_t)rrow * NCATS + col] =
                make_float2(acc[mt][nt][0], acc[mt][nt][1]);
            *(float2*)&out[obase + (size_t)(rrow + 8) * NCATS + col] =
                make_float2(acc[mt][nt][2], acc[mt][nt][3]);
        }
    }
}

// ---------------- launch ----------------
extern "C" void kernel_launch(void* const* d_in, const int* in_sizes, int n_in,
                              void* d_out, int out_size) {
    const void*  x      = d_in[0];
    const float* emb    = (const float*)d_in[1];
    const float* Wi     = (const float*)d_in[2];
    const float* bi     = (const float*)d_in[3];
    const float* Whrz   = (const float*)d_in[4];
    const float* Whn    = (const float*)d_in[5];
    const float* bhn    = (const float*)d_in[6];
    const float* Wcls   = (const float*)d_in[7];
    const float* bcls   = (const float*)d_in[8];
    const float* initst = (const float*)d_in[9];
    float* out = (float*)d_out;

    const int LOG_SMEM = (128 + 256) * HPAD * (int)sizeof(__half);   // 104448 B
    cudaFuncSetAttribute(logits_kernel, cudaFuncAttributeMaxDynamicSharedMemorySize, LOG_SMEM);

    detect_kernel<<<1, 256>>>((const unsigned int*)x);
    proj_kernel<<<257, DD>>>(emb, Wi, bi);
    prep_wc<<<(NCATS * DD) / 256, 256>>>(Wcls);
    scan_kernel<<<BS / 2, 256>>>((const int*)x, Whrz, Whn, bhn, initst);
    logits_kernel<<<dim3(SEQ / 128, BS), 512, LOG_SMEM>>>(bcls, out);
}

// round 15
// speedup vs baseline: 1.9576x; 1.0689x over previous
#include <cuda_runtime.h>
#include <cuda_fp16.h>
#include <stdint.h>

// ---------------- problem constants ----------------
#define BS    256
#define SEQ   4096
#define DD    128
#define NCATS 256
#define GCOLS 384

// ---------------- device scratch ----------------
__device__ __half g_Hh[(size_t)BS * SEQ * DD];   // hidden history, fp16 (for logits GEMM)
__device__ float  g_proj4[257 * DD * 4];         // per-token xi: [tok][d][{xr,xz,xn,0}]
__device__ __half g_WcT[NCATS * DD];             // W_cls transposed -> [cat][d], fp16
__device__ int    g_is64;

// ---------------- helpers ----------------
__device__ __forceinline__ uint32_t smem_u32(const void* p) {
    uint32_t a;
    asm("{ .reg .u64 t; cvta.to.shared.u64 t, %1; cvt.u32.u64 %0, t; }" : "=r"(a) : "l"(p));
    return a;
}
__device__ __forceinline__ uint32_t packh2(float a, float b) {
    __half2 h = __floats2half2_rn(a, b);
    return *reinterpret_cast<uint32_t*>(&h);
}
__device__ __forceinline__ void mma16816(float* d, const uint32_t* a, const uint32_t* b) {
    asm volatile(
        "mma.sync.aligned.m16n8k16.row.col.f32.f16.f16.f32 "
        "{%0,%1,%2,%3}, {%4,%5,%6,%7}, {%8,%9}, {%0,%1,%2,%3};\n"
        : "+f"(d[0]), "+f"(d[1]), "+f"(d[2]), "+f"(d[3])
        : "r"(a[0]), "r"(a[1]), "r"(a[2]), "r"(a[3]), "r"(b[0]), "r"(b[1]));
}
__device__ __forceinline__ void ldsm_x4(uint32_t* r, uint32_t addr) {
    asm volatile("ldmatrix.sync.aligned.m8n8.x4.shared.b16 {%0,%1,%2,%3}, [%4];"
                 : "=r"(r[0]), "=r"(r[1]), "=r"(r[2]), "=r"(r[3]) : "r"(addr));
}
__device__ __forceinline__ float ex2f(float x) {
    float y; asm("ex2.approx.f32 %0, %1;" : "=f"(y) : "f"(x)); return y;
}
__device__ __forceinline__ float rcpf(float x) {
    float y; asm("rcp.approx.f32 %0, %1;" : "=f"(y) : "f"(x)); return y;
}
__device__ __forceinline__ float tanh_mufu(float x) {
    float y; asm("tanh.approx.f32 %0, %1;" : "=f"(y) : "f"(x)); return y;
}
// sigmoid via single-MUFU tanh: sig(x) = 0.5 + 0.5*tanh(0.5x)
__device__ __forceinline__ float sig_mufu(float x) {
    return fmaf(0.5f, tanh_mufu(0.5f * x), 0.5f);
}
// exact-ish tanh for the N gate (kept on ex2/rcp path)
__device__ __forceinline__ float tanhf_fast(float x) {
    return 1.f - 2.f * rcpf(1.f + ex2f(2.8853900817779268f * x));
}

// ---------------- kernel 1: int64/int32 detection ----------------
__global__ void detect_kernel(const unsigned int* xw) {
    __shared__ unsigned int s[256];
    unsigned int v = 0;
    for (int i = threadIdx.x; i < 4096; i += 256) v |= xw[2 * i + 1];
    s[threadIdx.x] = v;
    __syncthreads();
    if (threadIdx.x == 0) {
        unsigned int a = 0;
        for (int i = 0; i < 256; i++) a |= s[i];
        g_is64 = (a == 0) ? 1 : 0;
    }
}

// ---------------- kernel 2: proj4[c][d] = (xr, xz, xn, 0) ----------------
__global__ void __launch_bounds__(DD) proj_kernel(const float* __restrict__ emb,
                                                  const float* __restrict__ Wi,
                                                  const float* __restrict__ bi) {
    __shared__ float e[DD];
    const int c = blockIdx.x;
    const int j = threadIdx.x;
    e[j] = emb[c * DD + j];
    __syncthreads();
    float a0 = bi[j], a1 = bi[DD + j], a2 = bi[2 * DD + j];
#pragma unroll 8
    for (int k = 0; k < DD; k++) {
        float ek = e[k];
        a0 += ek * Wi[k * GCOLS + j];
        a1 += ek * Wi[k * GCOLS + DD + j];
        a2 += ek * Wi[k * GCOLS + 2 * DD + j];
    }
    float4* o = (float4*)&g_proj4[(size_t)(c * DD + j) * 4];
    *o = make_float4(a0, a1, a2, 0.f);
}

// ---------------- kernel 2b: W_cls -> fp16 transposed ----------------
__global__ void prep_wc(const float* __restrict__ Wcls) {
    int i = blockIdx.x * 256 + threadIdx.x;      // 32768
    int d = i / NCATS, c = i % NCATS;
    g_WcT[c * DD + d] = __float2half_rn(Wcls[d * NCATS + c]);
}

// ---------------- kernel 3: HMMA GRU scan, 128 CTAs x 2 rows (exact R12 + MUFU sigmoids) ----------------
#define HTP 136   // padded hT row (halves) -> 272B stride
__global__ void __launch_bounds__(256, 1)
scan_kernel(const int* __restrict__ xw,
            const float* __restrict__ Whrz,
            const float* __restrict__ Whn,
            const float* __restrict__ bhn,
            const float* __restrict__ initst) {
    __shared__ __half hT[2][2][HTP];    // [buf][row][k]

    const int tid = threadIdx.x;
    const int w = tid >> 5, l = tid & 31;
    const int gr = l >> 2, q = l & 3;
    const int row0 = blockIdx.x * 2;
    const int d   = w * 16 + gr + ((q & 2) ? 8 : 0);  // this lane's gate dim
    const int row = q & 1;                            // this lane's batch row

    // ---- A fragments: warp w holds r,z,n for its d-range ----
    uint32_t A[3][8][4];
    {
        const int kc = q * 2;
#pragma unroll
        for (int s = 0; s < 3; s++) {
#pragma unroll
            for (int kt = 0; kt < 8; kt++) {
                const int k0 = kt * 16 + kc;
                float a00, a01, a10, a11, a20, a21, a30, a31;
                if (s == 2) {
                    int ga = w * 16 + gr, gb = ga + 8;
                    a00 = Whn[k0 * DD + ga];       a01 = Whn[(k0 + 1) * DD + ga];
                    a10 = Whn[k0 * DD + gb];       a11 = Whn[(k0 + 1) * DD + gb];
                    a20 = Whn[(k0 + 8) * DD + ga]; a21 = Whn[(k0 + 9) * DD + ga];
                    a30 = Whn[(k0 + 8) * DD + gb]; a31 = Whn[(k0 + 9) * DD + gb];
                } else {
                    int ga = s * 128 + w * 16 + gr, gb = ga + 8;
                    a00 = Whrz[k0 * 256 + ga];       a01 = Whrz[(k0 + 1) * 256 + ga];
                    a10 = Whrz[k0 * 256 + gb];       a11 = Whrz[(k0 + 1) * 256 + gb];
                    a20 = Whrz[(k0 + 8) * 256 + ga]; a21 = Whrz[(k0 + 9) * 256 + ga];
                    a30 = Whrz[(k0 + 8) * 256 + gb]; a31 = Whrz[(k0 + 9) * 256 + gb];
                }
                A[s][kt][0] = packh2(a00, a01);
                A[s][kt][1] = packh2(a10, a11);
                A[s][kt][2] = packh2(a20, a21);
                A[s][kt][3] = packh2(a30, a31);
            }
        }
    }

    // ---- init ----
    float h = initst[d];
    const float bn = bhn[d];
    hT[0][row][d] = __float2half_rn(h);
    float4 xi = *(const float4*)&g_proj4[(size_t)(NCATS * DD + d) * 4];   // BOS
    const int is64 = g_is64;
    const int xbase = (row0 + row) * SEQ;
    int tok = is64 ? xw[2 * xbase] : xw[xbase];
    __syncthreads();

    // lane's B-fragment base: n-col (l>>2) -> physical row (l>>2)&1 (broadcast)
    const uint32_t bOff = (uint32_t)(((l >> 2) & 1) * (HTP * 2) + q * 4);

    for (int t = 0; t < SEQ; t++) {
        // ---- B fragments from hT[t&1] ----
        const char* hb = (const char*)hT + (uint32_t)((t & 1) * (2 * HTP * 2)) + bOff;
        uint32_t b[8][2];
#pragma unroll
        for (int kt = 0; kt < 8; kt++) {
            b[kt][0] = *(const uint32_t*)(hb + kt * 32);
            b[kt][1] = *(const uint32_t*)(hb + kt * 32 + 16);
        }

        // ---- 24 MMAs, 6 independent chains ----
        float acc[3][2][4];
#pragma unroll
        for (int s = 0; s < 3; s++)
#pragma unroll
            for (int p = 0; p < 4; p++) { acc[s][0][p] = 0.f; acc[s][1][p] = 0.f; }
#pragma unroll
        for (int kt = 0; kt < 8; kt++)
#pragma unroll
            for (int s = 0; s < 3; s++) mma16816(acc[s][kt & 1], A[s][kt], b[kt]);

        // ---- prefetch next xi / token in the MMA drain shadow ----
        float4 xin = *(const float4*)&g_proj4[(size_t)(tok * DD + d) * 4];
        int tokn = tok;
        if (t + 1 < SEQ) {
            int idx = xbase + t + 1;
            tokn = is64 ? xw[2 * idx] : xw[idx];
        }

        // ---- register select of this lane's (d,row) pre-activations ----
        float pr, pz, pn;
        {
            float e0, e1;
            e0 = (q & 2) ? acc[0][0][2] : acc[0][0][0];
            e1 = (q & 2) ? acc[0][0][3] : acc[0][0][1];
            pr = ((q & 1) ? e1 : e0);
            e0 = (q & 2) ? acc[0][1][2] : acc[0][1][0];
            e1 = (q & 2) ? acc[0][1][3] : acc[0][1][1];
            pr += ((q & 1) ? e1 : e0);

            e0 = (q & 2) ? acc[1][0][2] : acc[1][0][0];
            e1 = (q & 2) ? acc[1][0][3] : acc[1][0][1];
            pz = ((q & 1) ? e1 : e0);
            e0 = (q & 2) ? acc[1][1][2] : acc[1][1][0];
            e1 = (q & 2) ? acc[1][1][3] : acc[1][1][1];
            pz += ((q & 1) ? e1 : e0);

            e0 = (q & 2) ? acc[2][0][2] : acc[2][0][0];
            e1 = (q & 2) ? acc[2][0][3] : acc[2][0][1];
            pn = ((q & 1) ? e1 : e0);
            e0 = (q & 2) ? acc[2][1][2] : acc[2][1][0];
            e1 = (q & 2) ? acc[2][1][3] : acc[2][1][1];
            pn += ((q & 1) ? e1 : e0);
        }

        // ---- gates: sigmoids on single-MUFU tanh path; N on ex2/rcp path ----
        float R = sig_mufu(xi.x + pr);
        float Z = sig_mufu(xi.y + pz);
        float N = tanhf_fast(xi.z + R * (pn + bn));
        h = N + Z * (h - N);

        __half hh = __float2half_rn(h);
        g_Hh[((size_t)(row0 + row) * SEQ + t) * DD + d] = hh;
        hT[(t + 1) & 1][row][d] = hh;      // write NEXT buffer
        xi = xin; tok = tokn;
        __syncthreads();                   // ONE barrier per step
    }
}

// ---------------- kernel 4: logits = H @ W_cls + b_cls via HMMA ----------------
// 128 t-rows x 128 cats per CTA, 256 threads, 2 CTAs/SM (regs capped by launch_bounds).
// blockIdx.x: bit0 = cat half, bits>=1 = t-tile. blockIdx.y = batch.
#define HPAD 136
__global__ void __launch_bounds__(256, 2) logits_kernel(const float* __restrict__ bcls,
                                                        float* __restrict__ out) {
    extern __shared__ __half sh[];
    __half* Hs = sh;                    // [128][HPAD]
    __half* Wc = sh + 128 * HPAD;       // [128][HPAD]  (WcT rows nbase..nbase+127)
    const int tid = threadIdx.x;
    const int batch = blockIdx.y;
    const int t0 = (blockIdx.x >> 1) * 128;
    const int nbase = (blockIdx.x & 1) * 128;

    const __half* hsrc = &g_Hh[((size_t)batch * SEQ + t0) * DD];
    for (int i = tid; i < 128 * 16; i += 256) {
        int rr = i >> 4, c8 = (i & 15) * 8;
        *(float4*)&Hs[rr * HPAD + c8] = *(const float4*)&hsrc[rr * DD + c8];
    }
    const __half* wsrc = &g_WcT[nbase * DD];
    for (int i = tid; i < 128 * 16; i += 256) {
        int rr = i >> 4, c8 = (i & 15) * 8;
        *(float4*)&Wc[rr * HPAD + c8] = *(const float4*)&wsrc[rr * DD + c8];
    }
    __syncthreads();

    const int w = tid >> 5, l = tid & 31;
    const int m0 = (w >> 2) * 64;       // 2 m-groups of 64 rows
    const int n0 = (w & 3) * 32;        // 4 n-groups of 32 cats

    float acc[4][4][4];
#pragma unroll
    for (int nt = 0; nt < 4; nt++) {
        float b0 = bcls[nbase + n0 + nt * 8 + (l & 3) * 2];
        float b1 = bcls[nbase + n0 + nt * 8 + (l & 3) * 2 + 1];
#pragma unroll
        for (int mt = 0; mt < 4; mt++) {
            acc[mt][nt][0] = b0; acc[mt][nt][1] = b1;
            acc[mt][nt][2] = b0; acc[mt][nt][3] = b1;
        }
    }

    const uint32_t hs_u32 = smem_u32(Hs);
    const int arow = m0 + (l & 15);
    const int acol = (l >> 4) * 8;
#pragma unroll
    for (int kt = 0; kt < 8; kt++) {
        uint32_t Af[4][4];
#pragma unroll
        for (int mt = 0; mt < 4; mt++)
            ldsm_x4(Af[mt], hs_u32 + (uint32_t)(((arow + mt * 16) * HPAD + kt * 16 + acol) * 2));
        uint32_t Bf[4][2];
#pragma unroll
        for (int nt = 0; nt < 4; nt++) {
            const __half* wp = &Wc[(n0 + nt * 8 + (l >> 2)) * HPAD + kt * 16 + (l & 3) * 2];
            Bf[nt][0] = *(const uint32_t*)wp;
            Bf[nt][1] = *(const uint32_t*)(wp + 8);
        }
#pragma unroll
        for (int mt = 0; mt < 4; mt++)
#pragma unroll
            for (int nt = 0; nt < 4; nt++) mma16816(acc[mt][nt], Af[mt], Bf[nt]);
    }

    const size_t obase = ((size_t)batch * SEQ + t0) * NCATS + nbase;
#pragma unroll
    for (int mt = 0; mt < 4; mt++) {
        const int rrow = m0 + mt * 16 + (l >> 2);
#pragma unroll
        for (int nt = 0; nt < 4; nt++) {
            const int col = n0 + nt * 8 + (l & 3) * 2;
            *(float2*)&out[obase + (size_t)rrow * NCATS + col] =
                make_float2(acc[mt][nt][0], acc[mt][nt][1]);
            *(float2*)&out[obase + (size_t)(rrow + 8) * NCATS + col] =
                make_float2(acc[mt][nt][2], acc[mt][nt][3]);
        }
    }
}

// ---------------- launch ----------------
extern "C" void kernel_launch(void* const* d_in, const int* in_sizes, int n_in,
                              void* d_out, int out_size) {
    const void*  x      = d_in[0];
    const float* emb    = (const float*)d_in[1];
    const float* Wi     = (const float*)d_in[2];
    const float* bi     = (const float*)d_in[3];
    const float* Whrz   = (const float*)d_in[4];
    const float* Whn    = (const float*)d_in[5];
    const float* bhn    = (const float*)d_in[6];
    const float* Wcls   = (const float*)d_in[7];
    const float* bcls   = (const float*)d_in[8];
    const float* initst = (const float*)d_in[9];
    float* out = (float*)d_out;

    const int LOG_SMEM = (128 + 128) * HPAD * (int)sizeof(__half);   // 69632 B
    cudaFuncSetAttribute(logits_kernel, cudaFuncAttributeMaxDynamicSharedMemorySize, LOG_SMEM);

    detect_kernel<<<1, 256>>>((const unsigned int*)x);
    proj_kernel<<<257, DD>>>(emb, Wi, bi);
    prep_wc<<<(NCATS * DD) / 256, 256>>>(Wcls);
    scan_kernel<<<BS / 2, 256>>>((const int*)x, Whrz, Whn, bhn, initst);
    logits_kernel<<<dim3((SEQ / 128) * 2, BS), 256, LOG_SMEM>>>(bcls, out);
}

// round 17
// speedup vs baseline: 2.0275x; 1.0358x over previous
#include <cuda_runtime.h>
#include <cuda_fp16.h>
#include <stdint.h>

// ---------------- problem constants ----------------
#define BS    256
#define SEQ   4096
#define DD    128
#define NCATS 256
#define GCOLS 384

// ---------------- device scratch ----------------
__device__ __half g_Hh[(size_t)BS * SEQ * DD];   // hidden history, fp16 (for logits GEMM)
__device__ float  g_proj4[257 * DD * 4];         // per-token xi: [tok][d][{xr,xz,xn,0}]
__device__ __half g_WcT[NCATS * DD];             // W_cls transposed -> [cat][d], fp16
__device__ int    g_is64;

// ---------------- helpers ----------------
__device__ __forceinline__ uint32_t smem_u32(const void* p) {
    uint32_t a;
    asm("{ .reg .u64 t; cvta.to.shared.u64 t, %1; cvt.u32.u64 %0, t; }" : "=r"(a) : "l"(p));
    return a;
}
__device__ __forceinline__ uint32_t packh2(float a, float b) {
    __half2 h = __floats2half2_rn(a, b);
    return *reinterpret_cast<uint32_t*>(&h);
}
__device__ __forceinline__ void mma16816(float* d, const uint32_t* a, const uint32_t* b) {
    asm volatile(
        "mma.sync.aligned.m16n8k16.row.col.f32.f16.f16.f32 "
        "{%0,%1,%2,%3}, {%4,%5,%6,%7}, {%8,%9}, {%0,%1,%2,%3};\n"
        : "+f"(d[0]), "+f"(d[1]), "+f"(d[2]), "+f"(d[3])
        : "r"(a[0]), "r"(a[1]), "r"(a[2]), "r"(a[3]), "r"(b[0]), "r"(b[1]));
}
__device__ __forceinline__ void ldsm_x4(uint32_t* r, uint32_t addr) {
    asm volatile("ldmatrix.sync.aligned.m8n8.x4.shared.b16 {%0,%1,%2,%3}, [%4];"
                 : "=r"(r[0]), "=r"(r[1]), "=r"(r[2]), "=r"(r[3]) : "r"(addr));
}
__device__ __forceinline__ float tanh_mufu(float x) {
    float y; asm("tanh.approx.f32 %0, %1;" : "=f"(y) : "f"(x)); return y;
}
// sigmoid via single-MUFU tanh: sig(x) = 0.5 + 0.5*tanh(0.5x)
__device__ __forceinline__ float sig_mufu(float x) {
    return fmaf(0.5f, tanh_mufu(0.5f * x), 0.5f);
}

// ---------------- kernel 1: int64/int32 detection ----------------
__global__ void detect_kernel(const unsigned int* xw) {
    __shared__ unsigned int s[256];
    unsigned int v = 0;
    for (int i = threadIdx.x; i < 4096; i += 256) v |= xw[2 * i + 1];
    s[threadIdx.x] = v;
    __syncthreads();
    if (threadIdx.x == 0) {
        unsigned int a = 0;
        for (int i = 0; i < 256; i++) a |= s[i];
        g_is64 = (a == 0) ? 1 : 0;
    }
}

// ---------------- kernel 2: proj4[c][d] = (xr, xz, xn, 0) ----------------
__global__ void __launch_bounds__(DD) proj_kernel(const float* __restrict__ emb,
                                                  const float* __restrict__ Wi,
                                                  const float* __restrict__ bi) {
    __shared__ float e[DD];
    const int c = blockIdx.x;
    const int j = threadIdx.x;
    e[j] = emb[c * DD + j];
    __syncthreads();
    float a0 = bi[j], a1 = bi[DD + j], a2 = bi[2 * DD + j];
#pragma unroll 8
    for (int k = 0; k < DD; k++) {
        float ek = e[k];
        a0 += ek * Wi[k * GCOLS + j];
        a1 += ek * Wi[k * GCOLS + DD + j];
        a2 += ek * Wi[k * GCOLS + 2 * DD + j];
    }
    float4* o = (float4*)&g_proj4[(size_t)(c * DD + j) * 4];
    *o = make_float4(a0, a1, a2, 0.f);
}

// ---------------- kernel 2b: W_cls -> fp16 transposed ----------------
__global__ void prep_wc(const float* __restrict__ Wcls) {
    int i = blockIdx.x * 256 + threadIdx.x;      // 32768
    int d = i / NCATS, c = i % NCATS;
    g_WcT[c * DD + d] = __float2half_rn(Wcls[d * NCATS + c]);
}

// ---------------- kernel 3: HMMA GRU scan, 128 CTAs x 2 rows (R15 + MUFU N-gate) ----------------
#define HTP 136   // padded hT row (halves) -> 272B stride
__global__ void __launch_bounds__(256, 1)
scan_kernel(const int* __restrict__ xw,
            const float* __restrict__ Whrz,
            const float* __restrict__ Whn,
            const float* __restrict__ bhn,
            const float* __restrict__ initst) {
    __shared__ __half hT[2][2][HTP];    // [buf][row][k]

    const int tid = threadIdx.x;
    const int w = tid >> 5, l = tid & 31;
    const int gr = l >> 2, q = l & 3;
    const int row0 = blockIdx.x * 2;
    const int d   = w * 16 + gr + ((q & 2) ? 8 : 0);  // this lane's gate dim
    const int row = q & 1;                            // this lane's batch row

    // ---- A fragments: warp w holds r,z,n for its d-range ----
    uint32_t A[3][8][4];
    {
        const int kc = q * 2;
#pragma unroll
        for (int s = 0; s < 3; s++) {
#pragma unroll
            for (int kt = 0; kt < 8; kt++) {
                const int k0 = kt * 16 + kc;
                float a00, a01, a10, a11, a20, a21, a30, a31;
                if (s == 2) {
                    int ga = w * 16 + gr, gb = ga + 8;
                    a00 = Whn[k0 * DD + ga];       a01 = Whn[(k0 + 1) * DD + ga];
                    a10 = Whn[k0 * DD + gb];       a11 = Whn[(k0 + 1) * DD + gb];
                    a20 = Whn[(k0 + 8) * DD + ga]; a21 = Whn[(k0 + 9) * DD + ga];
                    a30 = Whn[(k0 + 8) * DD + gb]; a31 = Whn[(k0 + 9) * DD + gb];
                } else {
                    int ga = s * 128 + w * 16 + gr, gb = ga + 8;
                    a00 = Whrz[k0 * 256 + ga];       a01 = Whrz[(k0 + 1) * 256 + ga];
                    a10 = Whrz[k0 * 256 + gb];       a11 = Whrz[(k0 + 1) * 256 + gb];
                    a20 = Whrz[(k0 + 8) * 256 + ga]; a21 = Whrz[(k0 + 9) * 256 + ga];
                    a30 = Whrz[(k0 + 8) * 256 + gb]; a31 = Whrz[(k0 + 9) * 256 + gb];
                }
                A[s][kt][0] = packh2(a00, a01);
                A[s][kt][1] = packh2(a10, a11);
                A[s][kt][2] = packh2(a20, a21);
                A[s][kt][3] = packh2(a30, a31);
            }
        }
    }

    // ---- init ----
    float h = initst[d];
    const float bn = bhn[d];
    hT[0][row][d] = __float2half_rn(h);
    float4 xi = *(const float4*)&g_proj4[(size_t)(NCATS * DD + d) * 4];   // BOS
    const int is64 = g_is64;
    const int xbase = (row0 + row) * SEQ;
    int tok = is64 ? xw[2 * xbase] : xw[xbase];
    __syncthreads();

    // lane's B-fragment base: n-col (l>>2) -> physical row (l>>2)&1 (broadcast)
    const uint32_t bOff = (uint32_t)(((l >> 2) & 1) * (HTP * 2) + q * 4);

    for (int t = 0; t < SEQ; t++) {
        // ---- B fragments from hT[t&1] ----
        const char* hb = (const char*)hT + (uint32_t)((t & 1) * (2 * HTP * 2)) + bOff;
        uint32_t b[8][2];
#pragma unroll
        for (int kt = 0; kt < 8; kt++) {
            b[kt][0] = *(const uint32_t*)(hb + kt * 32);
            b[kt][1] = *(const uint32_t*)(hb + kt * 32 + 16);
        }

        // ---- 24 MMAs, 6 independent chains ----
        float acc[3][2][4];
#pragma unroll
        for (int s = 0; s < 3; s++)
#pragma unroll
            for (int p = 0; p < 4; p++) { acc[s][0][p] = 0.f; acc[s][1][p] = 0.f; }
#pragma unroll
        for (int kt = 0; kt < 8; kt++)
#pragma unroll
            for (int s = 0; s < 3; s++) mma16816(acc[s][kt & 1], A[s][kt], b[kt]);

        // ---- prefetch next xi / token in the MMA drain shadow ----
        float4 xin = *(const float4*)&g_proj4[(size_t)(tok * DD + d) * 4];
        int tokn = tok;
        if (t + 1 < SEQ) {
            int idx = xbase + t + 1;
            tokn = is64 ? xw[2 * idx] : xw[idx];
        }

        // ---- register select of this lane's (d,row) pre-activations ----
        float pr, pz, pn;
        {
            float e0, e1;
            e0 = (q & 2) ? acc[0][0][2] : acc[0][0][0];
            e1 = (q & 2) ? acc[0][0][3] : acc[0][0][1];
            pr = ((q & 1) ? e1 : e0);
            e0 = (q & 2) ? acc[0][1][2] : acc[0][1][0];
            e1 = (q & 2) ? acc[0][1][3] : acc[0][1][1];
            pr += ((q & 1) ? e1 : e0);

            e0 = (q & 2) ? acc[1][0][2] : acc[1][0][0];
            e1 = (q & 2) ? acc[1][0][3] : acc[1][0][1];
            pz = ((q & 1) ? e1 : e0);
            e0 = (q & 2) ? acc[1][1][2] : acc[1][1][0];
            e1 = (q & 2) ? acc[1][1][3] : acc[1][1][1];
            pz += ((q & 1) ? e1 : e0);

            e0 = (q & 2) ? acc[2][0][2] : acc[2][0][0];
            e1 = (q & 2) ? acc[2][0][3] : acc[2][0][1];
            pn = ((q & 1) ? e1 : e0);
            e0 = (q & 2) ? acc[2][1][2] : acc[2][1][0];
            e1 = (q & 2) ? acc[2][1][3] : acc[2][1][1];
            pn += ((q & 1) ? e1 : e0);
        }

        // ---- gates: all three nonlinearities on single-MUFU tanh path ----
        float R = sig_mufu(xi.x + pr);
        float Z = sig_mufu(xi.y + pz);
        float N = tanh_mufu(xi.z + R * (pn + bn));
        h = N + Z * (h - N);

        __half hh = __float2half_rn(h);
        g_Hh[((size_t)(row0 + row) * SEQ + t) * DD + d] = hh;
        hT[(t + 1) & 1][row][d] = hh;      // write NEXT buffer
        xi = xin; tok = tokn;
        __syncthreads();                   // ONE barrier per step
    }
}

// ---------------- kernel 4: logits = H @ W_cls + b_cls via HMMA ----------------
// R11 shape (128 rows x 256 cats, 512 thr) + LDSM-based B-fragment loads:
// Wc [cat][d] is col-major (k,n) for mma's B operand -> ldmatrix.x4 non-trans.
#define HPAD 136
__global__ void __launch_bounds__(512, 1) logits_kernel(const float* __restrict__ bcls,
                                                        float* __restrict__ out) {
    extern __shared__ __half sh[];
    __half* Hs = sh;                    // [128][HPAD]
    __half* Wc = sh + 128 * HPAD;       // [256][HPAD]  (WcT: [cat][d])
    const int tid = threadIdx.x;
    const int batch = blockIdx.y;
    const int t0 = blockIdx.x * 128;

    const __half* hsrc = &g_Hh[((size_t)batch * SEQ + t0) * DD];
    for (int i = tid; i < 128 * 16; i += 512) {
        int rr = i >> 4, c8 = (i & 15) * 8;
        *(float4*)&Hs[rr * HPAD + c8] = *(const float4*)&hsrc[rr * DD + c8];
    }
    for (int i = tid; i < 256 * 16; i += 512) {
        int rr = i >> 4, c8 = (i & 15) * 8;
        *(float4*)&Wc[rr * HPAD + c8] = *(const float4*)&g_WcT[rr * DD + c8];
    }
    __syncthreads();

    const int w = tid >> 5, l = tid & 31;
    const int m0 = (w >> 2) * 32;       // 4 m-groups of 32 rows
    const int n0 = (w & 3) * 64;        // 4 n-groups of 64 cats

    float acc[2][8][4];
#pragma unroll
    for (int nt = 0; nt < 8; nt++) {
        float b0 = bcls[n0 + nt * 8 + (l & 3) * 2];
        float b1 = bcls[n0 + nt * 8 + (l & 3) * 2 + 1];
#pragma unroll
        for (int mt = 0; mt < 2; mt++) {
            acc[mt][nt][0] = b0; acc[mt][nt][1] = b1;
            acc[mt][nt][2] = b0; acc[mt][nt][3] = b1;
        }
    }

    const uint32_t hs_u32 = smem_u32(Hs);
    const uint32_t wc_u32 = smem_u32(Wc);
    const int arow = m0 + (l & 15);
    const int acol = (l >> 4) * 8;
    const int g8 = l >> 3;              // ldsm tile group 0..3
    const int r8 = l & 7;               // row within 8x8 tile
#pragma unroll
    for (int kt = 0; kt < 8; kt++) {
        uint32_t Af[2][4];
#pragma unroll
        for (int mt = 0; mt < 2; mt++)
            ldsm_x4(Af[mt], hs_u32 + (uint32_t)(((arow + mt * 16) * HPAD + kt * 16 + acol) * 2));
        // B fragments via ldmatrix: call c covers tiles (nt=c*2+(g8>>1), khalf=g8&1)
        uint32_t Bf[8][2];
#pragma unroll
        for (int c = 0; c < 4; c++) {
            const int nt_l = c * 2 + (g8 >> 1);
            const int half = g8 & 1;
            uint32_t r[4];
            ldsm_x4(r, wc_u32 + (uint32_t)(((n0 + nt_l * 8 + r8) * HPAD + kt * 16 + half * 8) * 2));
            Bf[c * 2][0]     = r[0];
            Bf[c * 2][1]     = r[1];
            Bf[c * 2 + 1][0] = r[2];
            Bf[c * 2 + 1][1] = r[3];
        }
#pragma unroll
        for (int mt = 0; mt < 2; mt++)
#pragma unroll
            for (int nt = 0; nt < 8; nt++) mma16816(acc[mt][nt], Af[mt], Bf[nt]);
    }

    const size_t obase = ((size_t)batch * SEQ + t0) * NCATS;
#pragma unroll
    for (int mt = 0; mt < 2; mt++) {
        const int rrow = m0 + mt * 16 + (l >> 2);
#pragma unroll
        for (int nt = 0; nt < 8; nt++) {
            const int col = n0 + nt * 8 + (l & 3) * 2;
            *(float2*)&out[obase + (size_t)rrow * NCATS + col] =
                make_float2(acc[mt][nt][0], acc[mt][nt][1]);
            *(float2*)&out[obase + (size_t)(rrow + 8) * NCATS + col] =
                make_float2(acc[mt][nt][2], acc[mt][nt][3]);
        }
    }
}

// ---------------- launch ----------------
extern "C" void kernel_launch(void* const* d_in, const int* in_sizes, int n_in,
                              void* d_out, int out_size) {
    const void*  x      = d_in[0];
    const float* emb    = (const float*)d_in[1];
    const float* Wi     = (const float*)d_in[2];
    const float* bi     = (const float*)d_in[3];
    const float* Whrz   = (const float*)d_in[4];
    const float* Whn    = (const float*)d_in[5];
    const float* bhn    = (const float*)d_in[6];
    const float* Wcls   = (const float*)d_in[7];
    const float* bcls   = (const float*)d_in[8];
    const float* initst = (const float*)d_in[9];
    float* out = (float*)d_out;

    const int LOG_SMEM = (128 + 256) * HPAD * (int)sizeof(__half);   // 104448 B
    cudaFuncSetAttribute(logits_kernel, cudaFuncAttributeMaxDynamicSharedMemorySize, LOG_SMEM);

    detect_kernel<<<1, 256>>>((const unsigned int*)x);
    proj_kernel<<<257, DD>>>(emb, Wi, bi);
    prep_wc<<<(NCATS * DD) / 256, 256>>>(Wcls);
    scan_kernel<<<BS / 2, 256>>>((const int*)x, Whrz, Whn, bhn, initst);
    logits_kernel<<<dim3(SEQ / 128, BS), 512, LOG_SMEM>>>(bcls, out);
}